// round 14
// baseline (speedup 1.0000x reference)
#include <cuda_runtime.h>
#include <cuda_fp16.h>
#include <math.h>
#include <stdint.h>

// ---------------- problem dims ----------------
#define Bq   4096
#define Tt   31
#define Cc   768
#define BDq  128
#define AUGq 384
#define NUq  256
#define HHq  64
#define NGq  512
#define OOq  12
#define TWq  11
#define BTq  (Bq*Tt) // 126976

// ---------------- device scratch ----------------
static __device__ __half g_xs_h [(size_t)Bq*Tt*Cc];
static __device__ __half g_ds_h [(size_t)Bq*Tt*Cc];
static __device__ __half g_dds_h[(size_t)Bq*Tt*Cc];
static __device__ float  g_xbar[(size_t)Bq*Cc];
static __device__ __half g_v_h [(size_t)Bq*Tt*AUGq];
static __device__ __half g_u_h [(size_t)Bq*Tt*NUq];
static __device__ __half g_ubar_h[(size_t)Bq*NUq];
static __device__ float  g_G   [(size_t)Bq*Tt*NGq];
static __device__ float  g_gbar[(size_t)Bq*NGq];
static __device__ float  g_winf[(size_t)Bq*TWq*HHq];
static __device__ float  g_winb[(size_t)Bq*TWq*HHq];
static __device__ float  g_linlog[(size_t)Bq*OOq];

// fp16 weights, [N][K] K-major (transposed)
static __device__ __half g_W3t[(size_t)AUGq*Cc];   // [cls|delta|acc] row blocks of 128
static __device__ __half g_L0t[(size_t)NUq*AUGq];
static __device__ __half g_Wt [(size_t)NGq*NUq];

// ---------------- helpers ----------------
__device__ __forceinline__ float geluf(float x) {
    return 0.5f * x * (1.0f + erff(x * 0.7071067811865476f));
}
__device__ __forceinline__ float sigf(float x) { return 1.0f / (1.0f + expf(-x)); }

__device__ __forceinline__ float blksum128(float v, volatile float* sw) {
    #pragma unroll
    for (int o = 16; o > 0; o >>= 1) v += __shfl_down_sync(0xffffffffu, v, o);
    int lane = threadIdx.x & 31, w = threadIdx.x >> 5;
    __syncthreads();
    if (lane == 0) sw[w] = v;
    __syncthreads();
    return sw[0] + sw[1] + sw[2] + sw[3];
}

__device__ __forceinline__ void mma16816(float* c, const uint32_t* a, const uint32_t* b) {
    asm volatile(
        "mma.sync.aligned.m16n8k16.row.col.f32.f16.f16.f32 "
        "{%0,%1,%2,%3}, {%4,%5,%6,%7}, {%8,%9}, {%0,%1,%2,%3};"
        : "+f"(c[0]), "+f"(c[1]), "+f"(c[2]), "+f"(c[3])
        : "r"(a[0]), "r"(a[1]), "r"(a[2]), "r"(a[3]), "r"(b[0]), "r"(b[1]));
}

__device__ __forceinline__ void ldsm4(uint32_t& r0, uint32_t& r1, uint32_t& r2, uint32_t& r3,
                                      uint32_t addr) {
    asm volatile("ldmatrix.sync.aligned.m8n8.x4.shared.b16 {%0,%1,%2,%3}, [%4];"
                 : "=r"(r0), "=r"(r1), "=r"(r2), "=r"(r3) : "r"(addr));
}

__device__ __forceinline__ unsigned long long pk2f(float lo, float hi) {
    unsigned long long r;
    asm("mov.b64 %0, {%1, %2};" : "=l"(r) : "f"(lo), "f"(hi));
    return r;
}
__device__ __forceinline__ void upk2f(unsigned long long v, float& lo, float& hi) {
    asm("mov.b64 {%0, %1}, %2;" : "=f"(lo), "=f"(hi) : "l"(v));
}
#define FMA2(acc, a, b) asm("fma.rn.f32x2 %0, %1, %2, %0;" : "+l"(acc) : "l"(a), "l"(b))

// ---------------- smem geometry for HMMA GEMM ----------------
// tile 128x128, BK=64 halves. row stride 144B (16B-aligned cp.async; LDSM conflict-free)
#define H_STRIDE 144
#define H_MAT    (128 * H_STRIDE)      // 18432
#define H_STAGE  (2 * H_MAT)           // 36864 (A + B)
#define H_NSTG   3
#define H_SMEM   (H_NSTG * H_STAGE)    // 110592, 3-stage pipeline

// mainloop: cp.async 3-stage, BK=64, ldmatrix fragments, computes 128x128 tile.
__device__ __forceinline__ void hmma_mainloop(
    const __half* __restrict__ A, const __half* __restrict__ Bt,
    int K, int m0, uint32_t sb, int tid, int lane,
    int warpM, int warpN, float acc[2][8][4]) {

    const int nc = K >> 6;

    auto issue = [&](int c) {
        const int k0 = c << 6;
        const uint32_t st = sb + (uint32_t)((c % H_NSTG) * H_STAGE);
        #pragma unroll
        for (int i = 0; i < 4; i++) {
            int id = (i << 8) + tid;            // 0..1023
            int r = id >> 3, c16 = id & 7;      // 8 x 16B per 128B row
            const __half* ga = A + (size_t)(m0 + r) * K + k0 + (c16 << 3);
            const __half* gb = Bt + (size_t)r * K + k0 + (c16 << 3);
            uint32_t da = st + r * H_STRIDE + (c16 << 4);
            asm volatile("cp.async.ca.shared.global [%0], [%1], 16;" :: "r"(da), "l"(ga));
            asm volatile("cp.async.ca.shared.global [%0], [%1], 16;" :: "r"(da + (uint32_t)H_MAT), "l"(gb));
        }
        asm volatile("cp.async.commit_group;" ::: "memory");
    };

    const uint32_t aRow = (uint32_t)(warpM + (lane & 15));
    const uint32_t aCol = (uint32_t)((lane >> 4) << 4);
    const uint32_t bRow = (uint32_t)(warpN + (lane & 7) + ((lane >> 4) << 3));
    const uint32_t bCol = (uint32_t)(((lane >> 3) & 1) << 4);

    auto compute = [&](int c) {
        const uint32_t st = sb + (uint32_t)((c % H_NSTG) * H_STAGE);
        #pragma unroll
        for (int ks = 0; ks < 4; ks++) {
            const uint32_t kB = (uint32_t)(ks << 5);   // 32B per k-step of 16 halves
            uint32_t a[2][4];
            #pragma unroll
            for (int mi = 0; mi < 2; mi++)
                ldsm4(a[mi][0], a[mi][1], a[mi][2], a[mi][3],
                      st + (aRow + (mi << 4)) * H_STRIDE + aCol + kB);
            uint32_t b[8][2];
            #pragma unroll
            for (int nj = 0; nj < 4; nj++)
                ldsm4(b[2 * nj][0], b[2 * nj][1], b[2 * nj + 1][0], b[2 * nj + 1][1],
                      st + (uint32_t)H_MAT + (bRow + (nj << 4)) * H_STRIDE + bCol + kB);
            #pragma unroll
            for (int mi = 0; mi < 2; mi++)
                #pragma unroll
                for (int ni = 0; ni < 8; ni++)
                    mma16816(acc[mi][ni], a[mi], b[ni]);
        }
    };

    issue(0);
    if (nc > 1) issue(1);
    for (int c = 0; c < nc; c++) {
        if (c + 1 < nc) asm volatile("cp.async.wait_group 1;" ::: "memory");
        else            asm volatile("cp.async.wait_group 0;" ::: "memory");
        __syncthreads();
        if (c + 2 < nc) issue(c + 2);
        compute(c);
    }
}

// ---------------- generic GEMM (EPI 0 raw / 1 gelu+bias) ----------------
template<int EPI, typename OutT>
__global__ __launch_bounds__(256, 2)
void gemm_h(const __half* __restrict__ A, const __half* __restrict__ Bt,
            OutT* __restrict__ Cm, int M, int N, int K, int ldC,
            const float* __restrict__ bias) {
    extern __shared__ char smem[];
    uint32_t sb;
    asm("{ .reg .u64 t; cvta.to.shared.u64 t, %1; cvt.u32.u64 %0, t; }" : "=r"(sb) : "l"(smem));
    const int tid = threadIdx.x, wid = tid >> 5, lane = tid & 31;
    const int grp = lane >> 2, tig = lane & 3;
    const int m0 = blockIdx.y << 7, n0 = blockIdx.x << 7;
    const int warpM = (wid >> 1) << 5, warpN = (wid & 1) << 6;

    float acc[2][8][4];
    #pragma unroll
    for (int mi = 0; mi < 2; mi++)
        #pragma unroll
        for (int ni = 0; ni < 8; ni++)
            #pragma unroll
            for (int q = 0; q < 4; q++) acc[mi][ni][q] = 0.0f;

    hmma_mainloop(A, Bt + (size_t)n0 * K, K, m0, sb, tid, lane, warpM, warpN, acc);

    #pragma unroll
    for (int mi = 0; mi < 2; mi++) {
        #pragma unroll
        for (int ni = 0; ni < 8; ni++) {
            int m = m0 + warpM + (mi << 4) + grp;
            int n = n0 + warpN + (ni << 3) + (tig << 1);
            float c0 = acc[mi][ni][0], c1 = acc[mi][ni][1];
            float c2 = acc[mi][ni][2], c3 = acc[mi][ni][3];
            if (EPI == 1) {
                float b0 = bias[n], b1 = bias[n + 1];
                c0 = geluf(c0 + b0); c1 = geluf(c1 + b1);
                c2 = geluf(c2 + b0); c3 = geluf(c3 + b1);
            }
            if (sizeof(OutT) == 2) {
                *reinterpret_cast<__half2*>((__half*)Cm + (size_t)m * ldC + n) = __floats2half2_rn(c0, c1);
                *reinterpret_cast<__half2*>((__half*)Cm + (size_t)(m + 8) * ldC + n) = __floats2half2_rn(c2, c3);
            } else {
                float2 v0; v0.x = c0; v0.y = c1;
                float2 v1; v1.x = c2; v1.y = c3;
                *reinterpret_cast<float2*>((float*)Cm + (size_t)m * ldC + n) = v0;
                *reinterpret_cast<float2*>((float*)Cm + (size_t)(m + 8) * ldC + n) = v1;
            }
        }
    }
}

// ---------------- merged stream GEMM: 3 streams in one launch, fused gelu+LN -------
__global__ __launch_bounds__(256, 2)
void gemm_streams(const __half* __restrict__ A0, const __half* __restrict__ A1,
                  const __half* __restrict__ A2, const __half* __restrict__ BtBase,
                  __half* __restrict__ Cm, int K,
                  const float* __restrict__ b0p, const float* __restrict__ b1p,
                  const float* __restrict__ b2p,
                  const float* __restrict__ g0p, const float* __restrict__ g1p,
                  const float* __restrict__ g2p,
                  const float* __restrict__ q0p, const float* __restrict__ q1p,
                  const float* __restrict__ q2p) {
    extern __shared__ char smem[];
    uint32_t sb;
    asm("{ .reg .u64 t; cvta.to.shared.u64 t, %1; cvt.u32.u64 %0, t; }" : "=r"(sb) : "l"(smem));
    const int tid = threadIdx.x, wid = tid >> 5, lane = tid & 31;
    const int grp = lane >> 2, tig = lane & 3;
    const int s = blockIdx.x;                 // stream 0..2
    const int m0 = blockIdx.y << 7;
    const int warpM = (wid >> 1) << 5, warpN = (wid & 1) << 6;
    const int cOff = s << 7;

    const __half* A   = (s == 0) ? A0 : (s == 1) ? A1 : A2;
    const __half* Bt  = BtBase + (size_t)cOff * K;
    const float* bias = (s == 0) ? b0p : (s == 1) ? b1p : b2p;
    const float* lng  = (s == 0) ? g0p : (s == 1) ? g1p : g2p;
    const float* lnb  = (s == 0) ? q0p : (s == 1) ? q1p : q2p;

    float acc[2][8][4];
    #pragma unroll
    for (int mi = 0; mi < 2; mi++)
        #pragma unroll
        for (int ni = 0; ni < 8; ni++)
            #pragma unroll
            for (int q = 0; q < 4; q++) acc[mi][ni][q] = 0.0f;

    hmma_mainloop(A, Bt, K, m0, sb, tid, lane, warpM, warpN, acc);

    // z = gelu(acc + bias)
    #pragma unroll
    for (int mi = 0; mi < 2; mi++)
        #pragma unroll
        for (int ni = 0; ni < 8; ni++) {
            int n = warpN + (ni << 3) + (tig << 1);
            float b0 = bias[n], b1 = bias[n + 1];
            acc[mi][ni][0] = geluf(acc[mi][ni][0] + b0);
            acc[mi][ni][1] = geluf(acc[mi][ni][1] + b1);
            acc[mi][ni][2] = geluf(acc[mi][ni][2] + b0);
            acc[mi][ni][3] = geluf(acc[mi][ni][3] + b1);
        }
    float* red  = reinterpret_cast<float*>(smem);   // [128][2]
    float* red2 = red + 256;
    __syncthreads();
    float rsum[2][2];
    #pragma unroll
    for (int mi = 0; mi < 2; mi++) {
        float s0 = 0.0f, s1 = 0.0f;
        #pragma unroll
        for (int ni = 0; ni < 8; ni++) {
            s0 += acc[mi][ni][0] + acc[mi][ni][1];
            s1 += acc[mi][ni][2] + acc[mi][ni][3];
        }
        s0 += __shfl_xor_sync(0xffffffffu, s0, 1);
        s0 += __shfl_xor_sync(0xffffffffu, s0, 2);
        s1 += __shfl_xor_sync(0xffffffffu, s1, 1);
        s1 += __shfl_xor_sync(0xffffffffu, s1, 2);
        rsum[mi][0] = s0; rsum[mi][1] = s1;
    }
    if (tig == 0) {
        #pragma unroll
        for (int mi = 0; mi < 2; mi++) {
            red[((warpM + (mi << 4) + grp) << 1) + (wid & 1)] = rsum[mi][0];
            red[((warpM + (mi << 4) + grp + 8) << 1) + (wid & 1)] = rsum[mi][1];
        }
    }
    __syncthreads();
    float mu[2][2];
    #pragma unroll
    for (int mi = 0; mi < 2; mi++) {
        int r0 = (warpM + (mi << 4) + grp) << 1;
        mu[mi][0] = (red[r0] + red[r0 + 1]) * (1.0f / 128.0f);
        mu[mi][1] = (red[r0 + 16] + red[r0 + 17]) * (1.0f / 128.0f);
    }
    float rvar[2][2];
    #pragma unroll
    for (int mi = 0; mi < 2; mi++) {
        float s0 = 0.0f, s1 = 0.0f;
        #pragma unroll
        for (int ni = 0; ni < 8; ni++) {
            float d0 = acc[mi][ni][0] - mu[mi][0], d1 = acc[mi][ni][1] - mu[mi][0];
            float d2 = acc[mi][ni][2] - mu[mi][1], d3 = acc[mi][ni][3] - mu[mi][1];
            s0 += d0 * d0 + d1 * d1;
            s1 += d2 * d2 + d3 * d3;
        }
        s0 += __shfl_xor_sync(0xffffffffu, s0, 1);
        s0 += __shfl_xor_sync(0xffffffffu, s0, 2);
        s1 += __shfl_xor_sync(0xffffffffu, s1, 1);
        s1 += __shfl_xor_sync(0xffffffffu, s1, 2);
        rvar[mi][0] = s0; rvar[mi][1] = s1;
    }
    if (tig == 0) {
        #pragma unroll
        for (int mi = 0; mi < 2; mi++) {
            red2[((warpM + (mi << 4) + grp) << 1) + (wid & 1)] = rvar[mi][0];
            red2[((warpM + (mi << 4) + grp + 8) << 1) + (wid & 1)] = rvar[mi][1];
        }
    }
    __syncthreads();
    #pragma unroll
    for (int mi = 0; mi < 2; mi++) {
        int r0 = (warpM + (mi << 4) + grp) << 1;
        float rs0 = rsqrtf((red2[r0] + red2[r0 + 1]) * (1.0f / 128.0f) + 1e-5f);
        float rs1 = rsqrtf((red2[r0 + 16] + red2[r0 + 17]) * (1.0f / 128.0f) + 1e-5f);
        int m = m0 + warpM + (mi << 4) + grp;
        #pragma unroll
        for (int ni = 0; ni < 8; ni++) {
            int n = warpN + (ni << 3) + (tig << 1);
            float g0 = lng[n], g1 = lng[n + 1];
            float bb0 = lnb[n], bb1 = lnb[n + 1];
            __half2 h0 = __floats2half2_rn(
                (acc[mi][ni][0] - mu[mi][0]) * rs0 * g0 + bb0,
                (acc[mi][ni][1] - mu[mi][0]) * rs0 * g1 + bb1);
            __half2 h1 = __floats2half2_rn(
                (acc[mi][ni][2] - mu[mi][1]) * rs1 * g0 + bb0,
                (acc[mi][ni][3] - mu[mi][1]) * rs1 * g1 + bb1);
            *reinterpret_cast<__half2*>(Cm + (size_t)m * AUGq + cOff + n) = h0;
            *reinterpret_cast<__half2*>(Cm + (size_t)(m + 8) * AUGq + cOff + n) = h1;
        }
    }
}

// ---------------- weight convert ----------------
__global__ void convert_b_kernel(const float* __restrict__ cls_w, const float* __restrict__ delta_w,
                                 const float* __restrict__ acc_w, const float* __restrict__ lin0_w,
                                 const float* __restrict__ wih_f, const float* __restrict__ wih_r) {
    int idx = blockIdx.x * blockDim.x + threadIdx.x;
    if (idx < AUGq * Cc) {
        int n = idx / Cc, c = idx % Cc;
        float w = (n < BDq) ? cls_w[c * BDq + n]
                : (n < 2 * BDq) ? delta_w[c * BDq + (n - BDq)]
                : acc_w[c * BDq + (n - 2 * BDq)];
        g_W3t[idx] = __float2half(w);
    }
    if (idx < NUq * AUGq) {
        int n = idx / AUGq, c = idx % AUGq;
        g_L0t[idx] = __float2half(lin0_w[c * NUq + n]);
    }
    if (idx < NGq * NUq) {
        int n = idx >> 8, c = idx & 255;
        float w = (n < 256) ? wih_f[c * 256 + n] : wih_r[c * 256 + (n - 256)];
        g_Wt[idx] = __float2half(w);
    }
}

// ---------------- EMA scan + time-domain streams + window mean ----------------
__global__ void ema_kernel(const float* __restrict__ x) {
    int idx = blockIdx.x * blockDim.x + threadIdx.x;
    if (idx >= Bq * Cc) return;
    int b = idx / Cc, c = idx % Cc;
    const size_t o = (size_t)b * Tt * Cc + c;
    const float* xp = x + o;

    float s0 = xp[0];
    g_xs_h[o] = __float2half(s0);
    float sp2 = 0.0f, sp1 = s0, s1 = 0.0f, s2 = 0.0f;
    float wsum = 0.0f;
    #pragma unroll
    for (int t = 1; t < Tt; t++) {
        float xt = xp[(size_t)t * Cc];
        float s = sp1 + 0.3f * (xt - sp1);
        size_t ot = o + (size_t)t * Cc;
        g_xs_h[ot] = __float2half(s);
        g_ds_h[ot] = __float2half(s - sp1);
        if (t == 1) {
            s1 = s;
            g_dds_h[ot] = __float2half(2.0f * (s - sp1));
        } else {
            if (t == 2) s2 = s;
            g_dds_h[ot] = __float2half(s - 2.0f * sp1 + sp2);
        }
        if (t >= 10 && t < 21) wsum += s;
        sp2 = sp1; sp1 = s;
    }
    g_ds_h[o]  = __float2half(s0 - s1);
    g_dds_h[o] = __float2half(s0 - 2.0f * s1 + s2);
    g_xbar[idx] = wsum * (1.0f / 11.0f);
}

// ---------------- time-mean of u ----------------
__global__ void ubar_kernel() {
    int idx = blockIdx.x * blockDim.x + threadIdx.x;
    if (idx >= Bq * NUq) return;
    int b = idx / NUq, n = idx % NUq;
    const __half* up = g_u_h + (size_t)b * Tt * NUq + n;
    float s = 0.0f;
    #pragma unroll
    for (int t = 0; t < Tt; t++) s += __half2float(up[(size_t)t * NUq]);
    g_ubar_h[idx] = __float2half(s * (1.0f / 31.0f));
}

// ---------------- BiLSTM (f32x2 packed gates) ----------------
#define RPB 8
__global__ __launch_bounds__(256) void lstm_kernel(const float* __restrict__ whh_f,
                                                   const float* __restrict__ b_f,
                                                   const float* __restrict__ whh_r,
                                                   const float* __restrict__ b_r) {
    const int dir = blockIdx.y;
    const int b0 = blockIdx.x * RPB;
    const int j = threadIdx.x;
    const float* whh  = dir ? whh_r : whh_f;
    const float* bias = dir ? b_r : b_f;
    const int off = dir ? 256 : 0;
    float* winbuf = dir ? g_winb : g_winf;

    float wcol[64];
    #pragma unroll
    for (int kk = 0; kk < 64; kk++) wcol[kk] = whh[kk * 256 + j];
    float base[RPB];
    #pragma unroll
    for (int r = 0; r < RPB; r++)
        base[r] = bias[j] - g_gbar[(size_t)(b0 + r) * NGq + off + j];

    // hs[kk][r]: 48B row stride (12 floats) -> 16B-aligned LDS.128, conflict-free STS.128
    __shared__ float hs[64][12];
    __shared__ float gs[RPB][256];
    if (j < 64) {
        #pragma unroll
        for (int r = 0; r < RPB; r++) hs[j][r] = 0.0f;
    }
    float creg[RPB];
    #pragma unroll
    for (int r = 0; r < RPB; r++) creg[r] = 0.0f;
    __syncthreads();

    for (int s = 0; s < Tt; s++) {
        int t = dir ? (Tt - 1 - s) : s;
        unsigned long long acc2[4];
        #pragma unroll
        for (int rp = 0; rp < 4; rp++) {
            float lo = base[2 * rp]     + g_G[((size_t)(b0 + 2 * rp)     * Tt + t) * NGq + off + j];
            float hi = base[2 * rp + 1] + g_G[((size_t)(b0 + 2 * rp + 1) * Tt + t) * NGq + off + j];
            acc2[rp] = pk2f(lo, hi);
        }
        #pragma unroll
        for (int kk = 0; kk < 64; kk++) {
            float4 ha = *reinterpret_cast<const float4*>(&hs[kk][0]);  // r0..r3
            float4 hb = *reinterpret_cast<const float4*>(&hs[kk][4]);  // r4..r7
            unsigned long long w2 = pk2f(wcol[kk], wcol[kk]);
            FMA2(acc2[0], w2, pk2f(ha.x, ha.y));
            FMA2(acc2[1], w2, pk2f(ha.z, ha.w));
            FMA2(acc2[2], w2, pk2f(hb.x, hb.y));
            FMA2(acc2[3], w2, pk2f(hb.z, hb.w));
        }
        #pragma unroll
        for (int rp = 0; rp < 4; rp++) {
            float lo, hi;
            upk2f(acc2[rp], lo, hi);
            gs[2 * rp][j] = lo;
            gs[2 * rp + 1][j] = hi;
        }
        __syncthreads();
        if (j < 64) {
            float harr[RPB];
            #pragma unroll
            for (int r = 0; r < RPB; r++) {
                float ig = sigf(gs[r][j]);
                float fg = sigf(gs[r][64 + j]);
                float gg = tanhf(gs[r][128 + j]);
                float og = sigf(gs[r][192 + j]);
                float c = fg * creg[r] + ig * gg;
                creg[r] = c;
                float h = og * tanhf(c);
                harr[r] = h;
                if (s >= 10 && s <= 20) {
                    int wt = dir ? (20 - s) : (s - 10);
                    winbuf[((size_t)(b0 + r) * TWq + wt) * HHq + j] = h;
                }
            }
            float4 h0; h0.x = harr[0]; h0.y = harr[1]; h0.z = harr[2]; h0.w = harr[3];
            float4 h1; h1.x = harr[4]; h1.y = harr[5]; h1.z = harr[6]; h1.w = harr[7];
            *reinterpret_cast<float4*>(&hs[j][0]) = h0;
            *reinterpret_cast<float4*>(&hs[j][4]) = h1;
        }
        __syncthreads();
    }
}

// ---------------- linear logits (exact fp32) ----------------
__global__ void linlog_kernel(const float* __restrict__ w, const float* __restrict__ bb) {
    int idx = blockIdx.x * blockDim.x + threadIdx.x;
    if (idx >= Bq * OOq) return;
    int b = idx / OOq, o = idx % OOq;
    const float* xb = g_xbar + (size_t)b * Cc;
    float s = bb[o];
    #pragma unroll 8
    for (int c = 0; c < Cc; c++) s += xb[c] * w[c * OOq + o];
    g_linlog[idx] = s;
}

// ---------------- attention + final gate ----------------
__global__ __launch_bounds__(128) void attn_final_kernel(
    const float* __restrict__ attn_w, const float* __restrict__ attn_b,
    const float* __restrict__ attn_temp, const float* __restrict__ lin2_w,
    const float* __restrict__ lin2_b, const float* __restrict__ gate,
    float* __restrict__ out) {
    __shared__ float red[4];
    __shared__ float att[128];
    int b = blockIdx.x, k = threadIdx.x;
    float win[TWq];
    const float* src = (k < HHq) ? (g_winf + (size_t)b * TWq * HHq + k)
                                 : (g_winb + (size_t)b * TWq * HHq + (k - HHq));
    #pragma unroll
    for (int t = 0; t < TWq; t++) win[t] = src[t * HHq];

    float aw = attn_w[k];
    float ab = attn_b[0];
    float temp = log1pf(expf(attn_temp[0])) + 0.001f;
    float sc[TWq];
    #pragma unroll
    for (int t = 0; t < TWq; t++)
        sc[t] = (blksum128(win[t] * aw, red) + ab) / temp;

    float mx = sc[0];
    #pragma unroll
    for (int t = 1; t < TWq; t++) mx = fmaxf(mx, sc[t]);
    float den = 0.0f;
    #pragma unroll
    for (int t = 0; t < TWq; t++) { sc[t] = expf(sc[t] - mx); den += sc[t]; }
    float inv = 1.0f / den;
    float at = 0.0f;
    #pragma unroll
    for (int t = 0; t < TWq; t++) at += sc[t] * inv * win[t];

    out[(size_t)Bq * OOq + (size_t)b * 128 + k] = at;
    att[k] = at;
    __syncthreads();
    if (k < OOq) {
        float s = lin2_b[k];
        #pragma unroll 8
        for (int kk = 0; kk < 128; kk++) s += att[kk] * lin2_w[kk * OOq + k];
        float lin = g_linlog[b * OOq + k];
        float gg = 1.0f / (1.0f + expf(-gate[0]));
        out[b * OOq + k] = lin + gg * (s - lin);
    }
}

// ---------------- launch ----------------
extern "C" void kernel_launch(void* const* d_in, const int* in_sizes, int n_in,
                              void* d_out, int out_size) {
    const float* x        = (const float*)d_in[0];
    const float* cls_w    = (const float*)d_in[1];
    const float* cls_b    = (const float*)d_in[2];
    const float* delta_w  = (const float*)d_in[3];
    const float* delta_b  = (const float*)d_in[4];
    const float* acc_w    = (const float*)d_in[5];
    const float* acc_b    = (const float*)d_in[6];
    const float* cls_ln_g = (const float*)d_in[7];
    const float* cls_ln_b = (const float*)d_in[8];
    const float* delta_ln_g = (const float*)d_in[9];
    const float* delta_ln_b = (const float*)d_in[10];
    const float* acc_ln_g = (const float*)d_in[11];
    const float* acc_ln_b = (const float*)d_in[12];
    const float* lin0_w   = (const float*)d_in[13];
    const float* lin0_b   = (const float*)d_in[14];
    const float* gate     = (const float*)d_in[15];
    const float* attn_w   = (const float*)d_in[16];
    const float* attn_b   = (const float*)d_in[17];
    const float* attn_temp= (const float*)d_in[18];
    const float* lin1_w   = (const float*)d_in[19];
    const float* lin1_b   = (const float*)d_in[20];
    const float* lin2_w   = (const float*)d_in[21];
    const float* lin2_b   = (const float*)d_in[22];
    const float* wih_f    = (const float*)d_in[23];
    const float* whh_f    = (const float*)d_in[24];
    const float* b_f      = (const float*)d_in[25];
    const float* wih_r    = (const float*)d_in[26];
    const float* whh_r    = (const float*)d_in[27];
    const float* b_r      = (const float*)d_in[28];
    float* out = (float*)d_out;

    __half *p_xs, *p_ds, *p_dds, *p_v, *p_u, *p_ubar, *p_W3, *p_L0, *p_W;
    float *p_G, *p_gbar;
    cudaGetSymbolAddress((void**)&p_xs,   g_xs_h);
    cudaGetSymbolAddress((void**)&p_ds,   g_ds_h);
    cudaGetSymbolAddress((void**)&p_dds,  g_dds_h);
    cudaGetSymbolAddress((void**)&p_v,    g_v_h);
    cudaGetSymbolAddress((void**)&p_u,    g_u_h);
    cudaGetSymbolAddress((void**)&p_ubar, g_ubar_h);
    cudaGetSymbolAddress((void**)&p_G,    g_G);
    cudaGetSymbolAddress((void**)&p_gbar, g_gbar);
    cudaGetSymbolAddress((void**)&p_W3,   g_W3t);
    cudaGetSymbolAddress((void**)&p_L0,   g_L0t);
    cudaGetSymbolAddress((void**)&p_W,    g_Wt);

    cudaFuncSetAttribute(gemm_streams,      cudaFuncAttributeMaxDynamicSharedMemorySize, H_SMEM);
    cudaFuncSetAttribute(gemm_h<1, __half>, cudaFuncAttributeMaxDynamicSharedMemorySize, H_SMEM);
    cudaFuncSetAttribute(gemm_h<0, float>,  cudaFuncAttributeMaxDynamicSharedMemorySize, H_SMEM);

    // 1. weights -> fp16 transposed
    convert_b_kernel<<<(AUGq * Cc + 255) / 256, 256>>>(cls_w, delta_w, acc_w, lin0_w, wih_f, wih_r);
    // 2. EMA + time-domain streams + window mean
    ema_kernel<<<(Bq * Cc + 255) / 256, 256>>>(x);
    // 3. merged stream GEMMs (3x: M=126976, N=128, K=768) + fused gelu+LN -> v (fp16)
    gemm_streams<<<dim3(3, BTq / 128), 256, H_SMEM>>>(
        p_xs, p_ds, p_dds, p_W3, p_v, Cc,
        cls_b, delta_b, acc_b,
        cls_ln_g, delta_ln_g, acc_ln_g,
        cls_ln_b, delta_ln_b, acc_ln_b);
    // 4. u = gelu(v @ lin0_w + b)   (126976 x 384 -> 256), fp16 out
    gemm_h<1, __half><<<dim3(NUq / 128, BTq / 128), 256, H_SMEM>>>(
        p_v, p_L0, p_u, BTq, NUq, AUGq, NUq, lin0_b);
    // 5. ubar = mean_t(u)
    ubar_kernel<<<(Bq * NUq + 255) / 256, 256>>>();
    // 6. G = u @ Wih   (126976 x 256 -> 512), fp32 out
    gemm_h<0, float><<<dim3(NGq / 128, BTq / 128), 256, H_SMEM>>>(
        p_u, p_W, p_G, BTq, NGq, NUq, NGq, nullptr);
    // 7. gbar = ubar @ Wih   (4096 x 256 -> 512), fp32 out
    gemm_h<0, float><<<dim3(NGq / 128, Bq / 128), 256, H_SMEM>>>(
        p_ubar, p_W, p_gbar, Bq, NGq, NUq, NGq, nullptr);
    // 8. BiLSTM recurrence (f32x2 gates)
    lstm_kernel<<<dim3(Bq / RPB, 2), 256>>>(whh_f, b_f, whh_r, b_r);
    // 9. linear logits (exact fp32)
    linlog_kernel<<<(Bq * OOq + 255) / 256, 256>>>(lin1_w, lin1_b);
    // 10. attention + final mix -> out
    attn_final_kernel<<<Bq, 128>>>(attn_w, attn_b, attn_temp, lin2_w, lin2_b, gate, out);
}

// round 16
// speedup vs baseline: 1.0656x; 1.0656x over previous
#include <cuda_runtime.h>
#include <cuda_fp16.h>
#include <math.h>
#include <stdint.h>

// ---------------- problem dims ----------------
#define Bq   4096
#define Tt   31
#define Cc   768
#define BDq  128
#define AUGq 384
#define NUq  256
#define HHq  64
#define NGq  512
#define OOq  12
#define TWq  11
#define BTq  (Bq*Tt) // 126976

// ---------------- device scratch ----------------
static __device__ __half g_xs_h [(size_t)Bq*Tt*Cc];
static __device__ __half g_ds_h [(size_t)Bq*Tt*Cc];
static __device__ __half g_dds_h[(size_t)Bq*Tt*Cc];
static __device__ float  g_xbar[(size_t)Bq*Cc];
static __device__ __half g_v_h [(size_t)Bq*Tt*AUGq];
static __device__ __half g_u_h [(size_t)Bq*Tt*NUq];
static __device__ __half g_ubar_h[(size_t)Bq*NUq];
static __device__ float  g_G   [(size_t)Bq*Tt*NGq];
static __device__ float  g_gbar[(size_t)Bq*NGq];
static __device__ float  g_winf[(size_t)Bq*TWq*HHq];
static __device__ float  g_winb[(size_t)Bq*TWq*HHq];
static __device__ float  g_linlog[(size_t)Bq*OOq];

// fp16 weights, [N][K] K-major (transposed)
static __device__ __half g_W3t[(size_t)AUGq*Cc];   // [cls|delta|acc] row blocks of 128
static __device__ __half g_L0t[(size_t)NUq*AUGq];
static __device__ __half g_Wt [(size_t)NGq*NUq];

// ---------------- helpers ----------------
__device__ __forceinline__ float geluf(float x) {
    return 0.5f * x * (1.0f + erff(x * 0.7071067811865476f));
}
__device__ __forceinline__ float sigf(float x) { return 1.0f / (1.0f + expf(-x)); }

__device__ __forceinline__ float blksum128(float v, volatile float* sw) {
    #pragma unroll
    for (int o = 16; o > 0; o >>= 1) v += __shfl_down_sync(0xffffffffu, v, o);
    int lane = threadIdx.x & 31, w = threadIdx.x >> 5;
    __syncthreads();
    if (lane == 0) sw[w] = v;
    __syncthreads();
    return sw[0] + sw[1] + sw[2] + sw[3];
}

__device__ __forceinline__ void mma16816(float* c, const uint32_t* a, const uint32_t* b) {
    asm volatile(
        "mma.sync.aligned.m16n8k16.row.col.f32.f16.f16.f32 "
        "{%0,%1,%2,%3}, {%4,%5,%6,%7}, {%8,%9}, {%0,%1,%2,%3};"
        : "+f"(c[0]), "+f"(c[1]), "+f"(c[2]), "+f"(c[3])
        : "r"(a[0]), "r"(a[1]), "r"(a[2]), "r"(a[3]), "r"(b[0]), "r"(b[1]));
}

__device__ __forceinline__ void ldsm4(uint32_t& r0, uint32_t& r1, uint32_t& r2, uint32_t& r3,
                                      uint32_t addr) {
    asm volatile("ldmatrix.sync.aligned.m8n8.x4.shared.b16 {%0,%1,%2,%3}, [%4];"
                 : "=r"(r0), "=r"(r1), "=r"(r2), "=r"(r3) : "r"(addr));
}

__device__ __forceinline__ unsigned long long pk2f(float lo, float hi) {
    unsigned long long r;
    asm("mov.b64 %0, {%1, %2};" : "=l"(r) : "f"(lo), "f"(hi));
    return r;
}
__device__ __forceinline__ void upk2f(unsigned long long v, float& lo, float& hi) {
    asm("mov.b64 {%0, %1}, %2;" : "=f"(lo), "=f"(hi) : "l"(v));
}
#define FMA2(acc, a, b) asm("fma.rn.f32x2 %0, %1, %2, %0;" : "+l"(acc) : "l"(a), "l"(b))

// ---------------- smem geometry for HMMA GEMM (R13 config) ----------------
// tile 128x128, BK=32 halves. row stride 80B (conflict-free LDSM/cp.async)
#define H_STRIDE 80
#define H_MAT    (128 * H_STRIDE)      // 10240
#define H_STAGE  (2 * H_MAT)           // 20480 (A + B)
#define H_NSTG   4
#define H_SMEM   (H_NSTG * H_STAGE)    // 81920, 4-stage pipeline

// mainloop: cp.async.cg 4-stage, ldmatrix fragments, computes 128x128 tile into acc.
__device__ __forceinline__ void hmma_mainloop(
    const __half* __restrict__ A, const __half* __restrict__ Bt,
    int K, int m0, uint32_t sb, int tid, int lane,
    int warpM, int warpN, float acc[2][8][4]) {

    const int nc = K >> 5;

    auto issue = [&](int c) {
        const int k0 = c << 5;
        const uint32_t st = sb + (uint32_t)((c % H_NSTG) * H_STAGE);
        #pragma unroll
        for (int i = 0; i < 2; i++) {
            int id = (i << 8) + tid;
            int r = id >> 2, c16 = id & 3;
            const __half* ga = A + (size_t)(m0 + r) * K + k0 + (c16 << 3);
            const __half* gb = Bt + (size_t)r * K + k0 + (c16 << 3);
            uint32_t da = st + r * H_STRIDE + (c16 << 4);
            asm volatile("cp.async.cg.shared.global [%0], [%1], 16;" :: "r"(da), "l"(ga));
            asm volatile("cp.async.cg.shared.global [%0], [%1], 16;" :: "r"(da + (uint32_t)H_MAT), "l"(gb));
        }
        asm volatile("cp.async.commit_group;" ::: "memory");
    };

    const uint32_t aRow = (uint32_t)(warpM + (lane & 15));
    const uint32_t aCol = (uint32_t)((lane >> 4) << 4);
    const uint32_t bRow = (uint32_t)(warpN + (lane & 7) + ((lane >> 4) << 3));
    const uint32_t bCol = (uint32_t)(((lane >> 3) & 1) << 4);

    auto compute = [&](int c) {
        const uint32_t st = sb + (uint32_t)((c % H_NSTG) * H_STAGE);
        #pragma unroll
        for (int ks = 0; ks < 2; ks++) {
            const uint32_t kB = (uint32_t)(ks << 5);
            uint32_t a[2][4];
            #pragma unroll
            for (int mi = 0; mi < 2; mi++)
                ldsm4(a[mi][0], a[mi][1], a[mi][2], a[mi][3],
                      st + (aRow + (mi << 4)) * H_STRIDE + aCol + kB);
            uint32_t b[8][2];
            #pragma unroll
            for (int nj = 0; nj < 4; nj++)
                ldsm4(b[2 * nj][0], b[2 * nj][1], b[2 * nj + 1][0], b[2 * nj + 1][1],
                      st + (uint32_t)H_MAT + (bRow + (nj << 4)) * H_STRIDE + bCol + kB);
            #pragma unroll
            for (int mi = 0; mi < 2; mi++)
                #pragma unroll
                for (int ni = 0; ni < 8; ni++)
                    mma16816(acc[mi][ni], a[mi], b[ni]);
        }
    };

    issue(0);
    if (nc > 1) issue(1);
    if (nc > 2) issue(2);
    for (int c = 0; c < nc; c++) {
        if (c + 2 < nc)      asm volatile("cp.async.wait_group 2;" ::: "memory");
        else if (c + 1 < nc) asm volatile("cp.async.wait_group 1;" ::: "memory");
        else                 asm volatile("cp.async.wait_group 0;" ::: "memory");
        __syncthreads();
        if (c + 3 < nc) issue(c + 3);
        compute(c);
    }
}

// ---------------- generic GEMM (EPI 0 raw / 1 gelu+bias) ----------------
template<int EPI, typename OutT>
__global__ __launch_bounds__(256, 2)
void gemm_h(const __half* __restrict__ A, const __half* __restrict__ Bt,
            OutT* __restrict__ Cm, int M, int N, int K, int ldC,
            const float* __restrict__ bias) {
    extern __shared__ char smem[];
    uint32_t sb;
    asm("{ .reg .u64 t; cvta.to.shared.u64 t, %1; cvt.u32.u64 %0, t; }" : "=r"(sb) : "l"(smem));
    const int tid = threadIdx.x, wid = tid >> 5, lane = tid & 31;
    const int grp = lane >> 2, tig = lane & 3;
    const int m0 = blockIdx.y << 7, n0 = blockIdx.x << 7;
    const int warpM = (wid >> 1) << 5, warpN = (wid & 1) << 6;

    float acc[2][8][4];
    #pragma unroll
    for (int mi = 0; mi < 2; mi++)
        #pragma unroll
        for (int ni = 0; ni < 8; ni++)
            #pragma unroll
            for (int q = 0; q < 4; q++) acc[mi][ni][q] = 0.0f;

    hmma_mainloop(A, Bt + (size_t)n0 * K, K, m0, sb, tid, lane, warpM, warpN, acc);

    #pragma unroll
    for (int mi = 0; mi < 2; mi++) {
        #pragma unroll
        for (int ni = 0; ni < 8; ni++) {
            int m = m0 + warpM + (mi << 4) + grp;
            int n = n0 + warpN + (ni << 3) + (tig << 1);
            float c0 = acc[mi][ni][0], c1 = acc[mi][ni][1];
            float c2 = acc[mi][ni][2], c3 = acc[mi][ni][3];
            if (EPI == 1) {
                float b0 = bias[n], b1 = bias[n + 1];
                c0 = geluf(c0 + b0); c1 = geluf(c1 + b1);
                c2 = geluf(c2 + b0); c3 = geluf(c3 + b1);
            }
            if (sizeof(OutT) == 2) {
                *reinterpret_cast<__half2*>((__half*)Cm + (size_t)m * ldC + n) = __floats2half2_rn(c0, c1);
                *reinterpret_cast<__half2*>((__half*)Cm + (size_t)(m + 8) * ldC + n) = __floats2half2_rn(c2, c3);
            } else {
                float2 v0; v0.x = c0; v0.y = c1;
                float2 v1; v1.x = c2; v1.y = c3;
                *reinterpret_cast<float2*>((float*)Cm + (size_t)m * ldC + n) = v0;
                *reinterpret_cast<float2*>((float*)Cm + (size_t)(m + 8) * ldC + n) = v1;
            }
        }
    }
}

// ---------------- G GEMM with folded gbar tail ----------------
// by < ySplit: C=G, A=u (M-tile by). by >= ySplit: C=gbar, A=ubar (M-tile by-ySplit).
__global__ __launch_bounds__(256, 2)
void gemm_G(const __half* __restrict__ U, const __half* __restrict__ Ubar,
            const __half* __restrict__ Bt, float* __restrict__ Gm, float* __restrict__ Gbar,
            int K, int ySplit) {
    extern __shared__ char smem[];
    uint32_t sb;
    asm("{ .reg .u64 t; cvta.to.shared.u64 t, %1; cvt.u32.u64 %0, t; }" : "=r"(sb) : "l"(smem));
    const int tid = threadIdx.x, wid = tid >> 5, lane = tid & 31;
    const int grp = lane >> 2, tig = lane & 3;
    const int by = blockIdx.y;
    const bool tail = (by >= ySplit);
    const __half* A = tail ? Ubar : U;
    float* Cm = tail ? Gbar : Gm;
    const int m0 = (tail ? (by - ySplit) : by) << 7;
    const int n0 = blockIdx.x << 7;
    const int warpM = (wid >> 1) << 5, warpN = (wid & 1) << 6;

    float acc[2][8][4];
    #pragma unroll
    for (int mi = 0; mi < 2; mi++)
        #pragma unroll
        for (int ni = 0; ni < 8; ni++)
            #pragma unroll
            for (int q = 0; q < 4; q++) acc[mi][ni][q] = 0.0f;

    hmma_mainloop(A, Bt + (size_t)n0 * K, K, m0, sb, tid, lane, warpM, warpN, acc);

    #pragma unroll
    for (int mi = 0; mi < 2; mi++) {
        #pragma unroll
        for (int ni = 0; ni < 8; ni++) {
            int m = m0 + warpM + (mi << 4) + grp;
            int n = n0 + warpN + (ni << 3) + (tig << 1);
            float2 v0; v0.x = acc[mi][ni][0]; v0.y = acc[mi][ni][1];
            float2 v1; v1.x = acc[mi][ni][2]; v1.y = acc[mi][ni][3];
            *reinterpret_cast<float2*>(Cm + (size_t)m * NGq + n) = v0;
            *reinterpret_cast<float2*>(Cm + (size_t)(m + 8) * NGq + n) = v1;
        }
    }
}

// ---------------- merged stream GEMM: 3 streams in one launch, fused gelu+LN -------
__global__ __launch_bounds__(256, 2)
void gemm_streams(const __half* __restrict__ A0, const __half* __restrict__ A1,
                  const __half* __restrict__ A2, const __half* __restrict__ BtBase,
                  __half* __restrict__ Cm, int K,
                  const float* __restrict__ b0p, const float* __restrict__ b1p,
                  const float* __restrict__ b2p,
                  const float* __restrict__ g0p, const float* __restrict__ g1p,
                  const float* __restrict__ g2p,
                  const float* __restrict__ q0p, const float* __restrict__ q1p,
                  const float* __restrict__ q2p) {
    extern __shared__ char smem[];
    uint32_t sb;
    asm("{ .reg .u64 t; cvta.to.shared.u64 t, %1; cvt.u32.u64 %0, t; }" : "=r"(sb) : "l"(smem));
    const int tid = threadIdx.x, wid = tid >> 5, lane = tid & 31;
    const int grp = lane >> 2, tig = lane & 3;
    const int s = blockIdx.x;                 // stream 0..2
    const int m0 = blockIdx.y << 7;
    const int warpM = (wid >> 1) << 5, warpN = (wid & 1) << 6;
    const int cOff = s << 7;

    const __half* A   = (s == 0) ? A0 : (s == 1) ? A1 : A2;
    const __half* Bt  = BtBase + (size_t)cOff * K;
    const float* bias = (s == 0) ? b0p : (s == 1) ? b1p : b2p;
    const float* lng  = (s == 0) ? g0p : (s == 1) ? g1p : g2p;
    const float* lnb  = (s == 0) ? q0p : (s == 1) ? q1p : q2p;

    float acc[2][8][4];
    #pragma unroll
    for (int mi = 0; mi < 2; mi++)
        #pragma unroll
        for (int ni = 0; ni < 8; ni++)
            #pragma unroll
            for (int q = 0; q < 4; q++) acc[mi][ni][q] = 0.0f;

    hmma_mainloop(A, Bt, K, m0, sb, tid, lane, warpM, warpN, acc);

    // z = gelu(acc + bias)
    #pragma unroll
    for (int mi = 0; mi < 2; mi++)
        #pragma unroll
        for (int ni = 0; ni < 8; ni++) {
            int n = warpN + (ni << 3) + (tig << 1);
            float b0 = bias[n], b1 = bias[n + 1];
            acc[mi][ni][0] = geluf(acc[mi][ni][0] + b0);
            acc[mi][ni][1] = geluf(acc[mi][ni][1] + b1);
            acc[mi][ni][2] = geluf(acc[mi][ni][2] + b0);
            acc[mi][ni][3] = geluf(acc[mi][ni][3] + b1);
        }
    float* red  = reinterpret_cast<float*>(smem);   // [128][2]
    float* red2 = red + 256;
    __syncthreads();
    float rsum[2][2];
    #pragma unroll
    for (int mi = 0; mi < 2; mi++) {
        float s0 = 0.0f, s1 = 0.0f;
        #pragma unroll
        for (int ni = 0; ni < 8; ni++) {
            s0 += acc[mi][ni][0] + acc[mi][ni][1];
            s1 += acc[mi][ni][2] + acc[mi][ni][3];
        }
        s0 += __shfl_xor_sync(0xffffffffu, s0, 1);
        s0 += __shfl_xor_sync(0xffffffffu, s0, 2);
        s1 += __shfl_xor_sync(0xffffffffu, s1, 1);
        s1 += __shfl_xor_sync(0xffffffffu, s1, 2);
        rsum[mi][0] = s0; rsum[mi][1] = s1;
    }
    if (tig == 0) {
        #pragma unroll
        for (int mi = 0; mi < 2; mi++) {
            red[((warpM + (mi << 4) + grp) << 1) + (wid & 1)] = rsum[mi][0];
            red[((warpM + (mi << 4) + grp + 8) << 1) + (wid & 1)] = rsum[mi][1];
        }
    }
    __syncthreads();
    float mu[2][2];
    #pragma unroll
    for (int mi = 0; mi < 2; mi++) {
        int r0 = (warpM + (mi << 4) + grp) << 1;
        mu[mi][0] = (red[r0] + red[r0 + 1]) * (1.0f / 128.0f);
        mu[mi][1] = (red[r0 + 16] + red[r0 + 17]) * (1.0f / 128.0f);
    }
    float rvar[2][2];
    #pragma unroll
    for (int mi = 0; mi < 2; mi++) {
        float s0 = 0.0f, s1 = 0.0f;
        #pragma unroll
        for (int ni = 0; ni < 8; ni++) {
            float d0 = acc[mi][ni][0] - mu[mi][0], d1 = acc[mi][ni][1] - mu[mi][0];
            float d2 = acc[mi][ni][2] - mu[mi][1], d3 = acc[mi][ni][3] - mu[mi][1];
            s0 += d0 * d0 + d1 * d1;
            s1 += d2 * d2 + d3 * d3;
        }
        s0 += __shfl_xor_sync(0xffffffffu, s0, 1);
        s0 += __shfl_xor_sync(0xffffffffu, s0, 2);
        s1 += __shfl_xor_sync(0xffffffffu, s1, 1);
        s1 += __shfl_xor_sync(0xffffffffu, s1, 2);
        rvar[mi][0] = s0; rvar[mi][1] = s1;
    }
    if (tig == 0) {
        #pragma unroll
        for (int mi = 0; mi < 2; mi++) {
            red2[((warpM + (mi << 4) + grp) << 1) + (wid & 1)] = rvar[mi][0];
            red2[((warpM + (mi << 4) + grp + 8) << 1) + (wid & 1)] = rvar[mi][1];
        }
    }
    __syncthreads();
    #pragma unroll
    for (int mi = 0; mi < 2; mi++) {
        int r0 = (warpM + (mi << 4) + grp) << 1;
        float rs0 = rsqrtf((red2[r0] + red2[r0 + 1]) * (1.0f / 128.0f) + 1e-5f);
        float rs1 = rsqrtf((red2[r0 + 16] + red2[r0 + 17]) * (1.0f / 128.0f) + 1e-5f);
        int m = m0 + warpM + (mi << 4) + grp;
        #pragma unroll
        for (int ni = 0; ni < 8; ni++) {
            int n = warpN + (ni << 3) + (tig << 1);
            float g0 = lng[n], g1 = lng[n + 1];
            float bb0 = lnb[n], bb1 = lnb[n + 1];
            __half2 h0 = __floats2half2_rn(
                (acc[mi][ni][0] - mu[mi][0]) * rs0 * g0 + bb0,
                (acc[mi][ni][1] - mu[mi][0]) * rs0 * g1 + bb1);
            __half2 h1 = __floats2half2_rn(
                (acc[mi][ni][2] - mu[mi][1]) * rs1 * g0 + bb0,
                (acc[mi][ni][3] - mu[mi][1]) * rs1 * g1 + bb1);
            *reinterpret_cast<__half2*>(Cm + (size_t)m * AUGq + cOff + n) = h0;
            *reinterpret_cast<__half2*>(Cm + (size_t)(m + 8) * AUGq + cOff + n) = h1;
        }
    }
}

// ---------------- weight convert ----------------
__global__ void convert_b_kernel(const float* __restrict__ cls_w, const float* __restrict__ delta_w,
                                 const float* __restrict__ acc_w, const float* __restrict__ lin0_w,
                                 const float* __restrict__ wih_f, const float* __restrict__ wih_r) {
    int idx = blockIdx.x * blockDim.x + threadIdx.x;
    if (idx < AUGq * Cc) {
        int n = idx / Cc, c = idx % Cc;
        float w = (n < BDq) ? cls_w[c * BDq + n]
                : (n < 2 * BDq) ? delta_w[c * BDq + (n - BDq)]
                : acc_w[c * BDq + (n - 2 * BDq)];
        g_W3t[idx] = __float2half(w);
    }
    if (idx < NUq * AUGq) {
        int n = idx / AUGq, c = idx % AUGq;
        g_L0t[idx] = __float2half(lin0_w[c * NUq + n]);
    }
    if (idx < NGq * NUq) {
        int n = idx >> 8, c = idx & 255;
        float w = (n < 256) ? wih_f[c * 256 + n] : wih_r[c * 256 + (n - 256)];
        g_Wt[idx] = __float2half(w);
    }
}

// ---------------- EMA scan + time-domain streams + window mean ----------------
__global__ void ema_kernel(const float* __restrict__ x) {
    int idx = blockIdx.x * blockDim.x + threadIdx.x;
    if (idx >= Bq * Cc) return;
    int b = idx / Cc, c = idx % Cc;
    const size_t o = (size_t)b * Tt * Cc + c;
    const float* xp = x + o;

    float s0 = xp[0];
    g_xs_h[o] = __float2half(s0);
    float sp2 = 0.0f, sp1 = s0, s1 = 0.0f, s2 = 0.0f;
    float wsum = 0.0f;
    #pragma unroll
    for (int t = 1; t < Tt; t++) {
        float xt = xp[(size_t)t * Cc];
        float s = sp1 + 0.3f * (xt - sp1);
        size_t ot = o + (size_t)t * Cc;
        g_xs_h[ot] = __float2half(s);
        g_ds_h[ot] = __float2half(s - sp1);
        if (t == 1) {
            s1 = s;
            g_dds_h[ot] = __float2half(2.0f * (s - sp1));
        } else {
            if (t == 2) s2 = s;
            g_dds_h[ot] = __float2half(s - 2.0f * sp1 + sp2);
        }
        if (t >= 10 && t < 21) wsum += s;
        sp2 = sp1; sp1 = s;
    }
    g_ds_h[o]  = __float2half(s0 - s1);
    g_dds_h[o] = __float2half(s0 - 2.0f * s1 + s2);
    g_xbar[idx] = wsum * (1.0f / 11.0f);
}

// ---------------- time-mean of u ----------------
__global__ void ubar_kernel() {
    int idx = blockIdx.x * blockDim.x + threadIdx.x;
    if (idx >= Bq * NUq) return;
    int b = idx / NUq, n = idx % NUq;
    const __half* up = g_u_h + (size_t)b * Tt * NUq + n;
    float s = 0.0f;
    #pragma unroll
    for (int t = 0; t < Tt; t++) s += __half2float(up[(size_t)t * NUq]);
    g_ubar_h[idx] = __float2half(s * (1.0f / 31.0f));
}

// ---------------- BiLSTM (f32x2 packed gates) ----------------
#define RPB 8
__global__ __launch_bounds__(256) void lstm_kernel(const float* __restrict__ whh_f,
                                                   const float* __restrict__ b_f,
                                                   const float* __restrict__ whh_r,
                                                   const float* __restrict__ b_r) {
    const int dir = blockIdx.y;
    const int b0 = blockIdx.x * RPB;
    const int j = threadIdx.x;
    const float* whh  = dir ? whh_r : whh_f;
    const float* bias = dir ? b_r : b_f;
    const int off = dir ? 256 : 0;
    float* winbuf = dir ? g_winb : g_winf;

    float wcol[64];
    #pragma unroll
    for (int kk = 0; kk < 64; kk++) wcol[kk] = whh[kk * 256 + j];
    float base[RPB];
    #pragma unroll
    for (int r = 0; r < RPB; r++)
        base[r] = bias[j] - g_gbar[(size_t)(b0 + r) * NGq + off + j];

    __shared__ float hs[64][12];   // hs[kk][r], 48B rows
    __shared__ float gs[RPB][256];
    if (j < 64) {
        #pragma unroll
        for (int r = 0; r < RPB; r++) hs[j][r] = 0.0f;
    }
    float creg[RPB];
    #pragma unroll
    for (int r = 0; r < RPB; r++) creg[r] = 0.0f;
    __syncthreads();

    for (int s = 0; s < Tt; s++) {
        int t = dir ? (Tt - 1 - s) : s;
        unsigned long long acc2[4];
        #pragma unroll
        for (int rp = 0; rp < 4; rp++) {
            float lo = base[2 * rp]     + g_G[((size_t)(b0 + 2 * rp)     * Tt + t) * NGq + off + j];
            float hi = base[2 * rp + 1] + g_G[((size_t)(b0 + 2 * rp + 1) * Tt + t) * NGq + off + j];
            acc2[rp] = pk2f(lo, hi);
        }
        #pragma unroll
        for (int kk = 0; kk < 64; kk++) {
            float4 ha = *reinterpret_cast<const float4*>(&hs[kk][0]);
            float4 hb = *reinterpret_cast<const float4*>(&hs[kk][4]);
            unsigned long long w2 = pk2f(wcol[kk], wcol[kk]);
            FMA2(acc2[0], w2, pk2f(ha.x, ha.y));
            FMA2(acc2[1], w2, pk2f(ha.z, ha.w));
            FMA2(acc2[2], w2, pk2f(hb.x, hb.y));
            FMA2(acc2[3], w2, pk2f(hb.z, hb.w));
        }
        #pragma unroll
        for (int rp = 0; rp < 4; rp++) {
            float lo, hi;
            upk2f(acc2[rp], lo, hi);
            gs[2 * rp][j] = lo;
            gs[2 * rp + 1][j] = hi;
        }
        __syncthreads();
        if (j < 64) {
            float harr[RPB];
            #pragma unroll
            for (int r = 0; r < RPB; r++) {
                float ig = sigf(gs[r][j]);
                float fg = sigf(gs[r][64 + j]);
                float gg = tanhf(gs[r][128 + j]);
                float og = sigf(gs[r][192 + j]);
                float c = fg * creg[r] + ig * gg;
                creg[r] = c;
                float h = og * tanhf(c);
                harr[r] = h;
                if (s >= 10 && s <= 20) {
                    int wt = dir ? (20 - s) : (s - 10);
                    winbuf[((size_t)(b0 + r) * TWq + wt) * HHq + j] = h;
                }
            }
            float4 h0; h0.x = harr[0]; h0.y = harr[1]; h0.z = harr[2]; h0.w = harr[3];
            float4 h1; h1.x = harr[4]; h1.y = harr[5]; h1.z = harr[6]; h1.w = harr[7];
            *reinterpret_cast<float4*>(&hs[j][0]) = h0;
            *reinterpret_cast<float4*>(&hs[j][4]) = h1;
        }
        __syncthreads();
    }
}

// ---------------- linear logits (exact fp32) ----------------
__global__ void linlog_kernel(const float* __restrict__ w, const float* __restrict__ bb) {
    int idx = blockIdx.x * blockDim.x + threadIdx.x;
    if (idx >= Bq * OOq) return;
    int b = idx / OOq, o = idx % OOq;
    const float* xb = g_xbar + (size_t)b * Cc;
    float s = bb[o];
    #pragma unroll 8
    for (int c = 0; c < Cc; c++) s += xb[c] * w[c * OOq + o];
    g_linlog[idx] = s;
}

// ---------------- attention + final gate ----------------
__global__ __launch_bounds__(128) void attn_final_kernel(
    const float* __restrict__ attn_w, const float* __restrict__ attn_b,
    const float* __restrict__ attn_temp, const float* __restrict__ lin2_w,
    const float* __restrict__ lin2_b, const float* __restrict__ gate,
    float* __restrict__ out) {
    __shared__ float red[4];
    __shared__ float att[128];
    int b = blockIdx.x, k = threadIdx.x;
    float win[TWq];
    const float* src = (k < HHq) ? (g_winf + (size_t)b * TWq * HHq + k)
                                 : (g_winb + (size_t)b * TWq * HHq + (k - HHq));
    #pragma unroll
    for (int t = 0; t < TWq; t++) win[t] = src[t * HHq];

    float aw = attn_w[k];
    float ab = attn_b[0];
    float temp = log1pf(expf(attn_temp[0])) + 0.001f;
    float sc[TWq];
    #pragma unroll
    for (int t = 0; t < TWq; t++)
        sc[t] = (blksum128(win[t] * aw, red) + ab) / temp;

    float mx = sc[0];
    #pragma unroll
    for (int t = 1; t < TWq; t++) mx = fmaxf(mx, sc[t]);
    float den = 0.0f;
    #pragma unroll
    for (int t = 0; t < TWq; t++) { sc[t] = expf(sc[t] - mx); den += sc[t]; }
    float inv = 1.0f / den;
    float at = 0.0f;
    #pragma unroll
    for (int t = 0; t < TWq; t++) at += sc[t] * inv * win[t];

    out[(size_t)Bq * OOq + (size_t)b * 128 + k] = at;
    att[k] = at;
    __syncthreads();
    if (k < OOq) {
        float s = lin2_b[k];
        #pragma unroll 8
        for (int kk = 0; kk < 128; kk++) s += att[kk] * lin2_w[kk * OOq + k];
        float lin = g_linlog[b * OOq + k];
        float gg = 1.0f / (1.0f + expf(-gate[0]));
        out[b * OOq + k] = lin + gg * (s - lin);
    }
}

// ---------------- launch ----------------
extern "C" void kernel_launch(void* const* d_in, const int* in_sizes, int n_in,
                              void* d_out, int out_size) {
    const float* x        = (const float*)d_in[0];
    const float* cls_w    = (const float*)d_in[1];
    const float* cls_b    = (const float*)d_in[2];
    const float* delta_w  = (const float*)d_in[3];
    const float* delta_b  = (const float*)d_in[4];
    const float* acc_w    = (const float*)d_in[5];
    const float* acc_b    = (const float*)d_in[6];
    const float* cls_ln_g = (const float*)d_in[7];
    const float* cls_ln_b = (const float*)d_in[8];
    const float* delta_ln_g = (const float*)d_in[9];
    const float* delta_ln_b = (const float*)d_in[10];
    const float* acc_ln_g = (const float*)d_in[11];
    const float* acc_ln_b = (const float*)d_in[12];
    const float* lin0_w   = (const float*)d_in[13];
    const float* lin0_b   = (const float*)d_in[14];
    const float* gate     = (const float*)d_in[15];
    const float* attn_w   = (const float*)d_in[16];
    const float* attn_b   = (const float*)d_in[17];
    const float* attn_temp= (const float*)d_in[18];
    const float* lin1_w   = (const float*)d_in[19];
    const float* lin1_b   = (const float*)d_in[20];
    const float* lin2_w   = (const float*)d_in[21];
    const float* lin2_b   = (const float*)d_in[22];
    const float* wih_f    = (const float*)d_in[23];
    const float* whh_f    = (const float*)d_in[24];
    const float* b_f      = (const float*)d_in[25];
    const float* wih_r    = (const float*)d_in[26];
    const float* whh_r    = (const float*)d_in[27];
    const float* b_r      = (const float*)d_in[28];
    float* out = (float*)d_out;

    __half *p_xs, *p_ds, *p_dds, *p_v, *p_u, *p_ubar, *p_W3, *p_L0, *p_W;
    float *p_G, *p_gbar;
    cudaGetSymbolAddress((void**)&p_xs,   g_xs_h);
    cudaGetSymbolAddress((void**)&p_ds,   g_ds_h);
    cudaGetSymbolAddress((void**)&p_dds,  g_dds_h);
    cudaGetSymbolAddress((void**)&p_v,    g_v_h);
    cudaGetSymbolAddress((void**)&p_u,    g_u_h);
    cudaGetSymbolAddress((void**)&p_ubar, g_ubar_h);
    cudaGetSymbolAddress((void**)&p_G,    g_G);
    cudaGetSymbolAddress((void**)&p_gbar, g_gbar);
    cudaGetSymbolAddress((void**)&p_W3,   g_W3t);
    cudaGetSymbolAddress((void**)&p_L0,   g_L0t);
    cudaGetSymbolAddress((void**)&p_W,    g_Wt);

    cudaFuncSetAttribute(gemm_streams,      cudaFuncAttributeMaxDynamicSharedMemorySize, H_SMEM);
    cudaFuncSetAttribute(gemm_h<1, __half>, cudaFuncAttributeMaxDynamicSharedMemorySize, H_SMEM);
    cudaFuncSetAttribute(gemm_G,            cudaFuncAttributeMaxDynamicSharedMemorySize, H_SMEM);

    // 1. weights -> fp16 transposed
    convert_b_kernel<<<(AUGq * Cc + 255) / 256, 256>>>(cls_w, delta_w, acc_w, lin0_w, wih_f, wih_r);
    // 2. EMA + time-domain streams + window mean
    ema_kernel<<<(Bq * Cc + 255) / 256, 256>>>(x);
    // 3. merged stream GEMMs (3x: M=126976, N=128, K=768) + fused gelu+LN -> v (fp16)
    gemm_streams<<<dim3(3, BTq / 128), 256, H_SMEM>>>(
        p_xs, p_ds, p_dds, p_W3, p_v, Cc,
        cls_b, delta_b, acc_b,
        cls_ln_g, delta_ln_g, acc_ln_g,
        cls_ln_b, delta_ln_b, acc_ln_b);
    // 4. u = gelu(v @ lin0_w + b)   (126976 x 384 -> 256), fp16 out
    gemm_h<1, __half><<<dim3(NUq / 128, BTq / 128), 256, H_SMEM>>>(
        p_v, p_L0, p_u, BTq, NUq, AUGq, NUq, lin0_b);
    // 5. ubar = mean_t(u)
    ubar_kernel<<<(Bq * NUq + 255) / 256, 256>>>();
    // 6. G = u @ Wih (fp32) with folded gbar tail (ubar @ Wih)
    gemm_G<<<dim3(NGq / 128, BTq / 128 + Bq / 128), 256, H_SMEM>>>(
        p_u, p_ubar, p_W, p_G, p_gbar, NUq, BTq / 128);
    // 7. BiLSTM recurrence (f32x2 gates)
    lstm_kernel<<<dim3(Bq / RPB, 2), 256>>>(whh_f, b_f, whh_r, b_r);
    // 8. linear logits (exact fp32)
    linlog_kernel<<<(Bq * OOq + 255) / 256, 256>>>(lin1_w, lin1_b);
    // 9. attention + final mix -> out
    attn_final_kernel<<<Bq, 128>>>(attn_w, attn_b, attn_temp, lin2_w, lin2_b, gate, out);
}